// round 12
// baseline (speedup 1.0000x reference)
#include <cuda_runtime.h>
#include <cstdint>

#define SCALE_F 0.08838834764831845f

// persistent split-bf16 KV tables (4096 rows x 256 elems), filled per launch
__device__ uint16_t g_kvh[4096 * 256];
__device__ uint16_t g_kvl[4096 * 256];

// ---------------- smem byte offsets ----------------
#define BUF(b) ((b) * 32768)
#define QT_H   65536     // Q hi: 32 rows x 256B
#define QT_L   73728     // Q lo
#define P_LO   65536     // P lo aliases QT (Q dead after phase A)
#define P_HI   81920     // P hi: 256 k x 64B (k-major)
#define REDM   98304
#define REDS   99328
#define INVV   100352
#define SIDX   100480
#define SMEM_BYTES 101504

// ---------------- helpers ----------------
static __device__ __forceinline__ uint32_t smem_u32(const void* p) {
    uint32_t a;
    asm("{ .reg .u64 t; cvta.to.shared.u64 t, %1; cvt.u32.u64 %0, t; }" : "=r"(a) : "l"(p));
    return a;
}
static __device__ __forceinline__ void ldm4(uint32_t* r, uint32_t addr) {
    asm volatile("ldmatrix.sync.aligned.m8n8.x4.shared.b16 {%0,%1,%2,%3}, [%4];"
                 : "=r"(r[0]), "=r"(r[1]), "=r"(r[2]), "=r"(r[3]) : "r"(addr));
}
static __device__ __forceinline__ void ldm4t(uint32_t* r, uint32_t addr) {
    asm volatile("ldmatrix.sync.aligned.m8n8.x4.trans.shared.b16 {%0,%1,%2,%3}, [%4];"
                 : "=r"(r[0]), "=r"(r[1]), "=r"(r[2]), "=r"(r[3]) : "r"(addr));
}
static __device__ __forceinline__ void mma16816(float* c, const uint32_t* a,
                                                uint32_t b0, uint32_t b1) {
    asm volatile("mma.sync.aligned.m16n8k16.row.col.f32.bf16.bf16.f32 "
                 "{%0,%1,%2,%3}, {%4,%5,%6,%7}, {%8,%9}, {%0,%1,%2,%3};"
                 : "+f"(c[0]), "+f"(c[1]), "+f"(c[2]), "+f"(c[3])
                 : "r"(a[0]), "r"(a[1]), "r"(a[2]), "r"(a[3]), "r"(b0), "r"(b1));
}
// pair split: H = packed (bf16t(x0), bf16t(x1)); L = packed rn-residuals
static __device__ __forceinline__ void sp2(float x0, float x1, uint32_t& H, uint32_t& L) {
    unsigned u0 = __float_as_uint(x0), u1 = __float_as_uint(x1);
    asm("prmt.b32 %0, %1, %2, 0x7632;" : "=r"(H) : "r"(u0), "r"(u1));
    float r0 = x0 - __uint_as_float(u0 & 0xFFFF0000u);
    float r1 = x1 - __uint_as_float(u1 & 0xFFFF0000u);
    asm("cvt.rn.bf16x2.f32 %0, %1, %2;" : "=r"(L) : "f"(r1), "f"(r0));
}
// k-major P byte offset for (k, h-chunk hc in 0..3): row 64B, XOR swizzle
static __device__ __forceinline__ uint32_t poff(int k, int hc) {
    return (uint32_t)(k * 64 + ((hc ^ ((k >> 1) & 3)) << 4));
}
#define CP_WAIT_ALL() asm volatile("cp.async.wait_group 0;" ::: "memory")

// ---- pre-kernel: split-convert the whole KV table once ----
__global__ void __launch_bounds__(256) cvt_kv_kernel(const float* __restrict__ kv) {
    int t = blockIdx.x * 256 + threadIdx.x;
    float4 v = *(const float4*)(kv + (long)t * 4);
    uint32_t H01, L01, H23, L23;
    sp2(v.x, v.y, H01, L01);
    sp2(v.z, v.w, H23, L23);
    *(uint2*)((char*)g_kvh + (long)t * 8) = make_uint2(H01, H23);
    *(uint2*)((char*)g_kvl + (long)t * 8) = make_uint2(L01, L23);
}

// issue cp.async for one 64-row half (hi+lo, 32KB) into buffer buf; all 256 threads
static __device__ __forceinline__ void issue_half(
    uint32_t sb, const int* sidx, int base /*0=K, 256=V bytes*/,
    int hc, int buf, int tid) {
#pragma unroll
    for (int i = 0; i < 8; i++) {
        int t = i * 256 + tid;
        int rc = t >> 4, c = t & 15;
        int half = rc >> 6, r = rc & 63;
        int id = sidx[hc * 64 + r];
        const uint16_t* tbl = half ? g_kvl : g_kvh;
        const char* src = (const char*)tbl + (long)id * 512 + base + c * 16;
        uint32_t dst = sb + BUF(buf) + half * 16384 + r * 256 + ((c ^ (r & 7)) << 4);
        asm volatile("cp.async.cg.shared.global [%0], [%1], 16;"
                     :: "r"(dst), "l"(__cvta_generic_to_global(src)));
    }
    asm volatile("cp.async.commit_group;");
}

// Phase A: warp (g row-group, nh h-half); M16 x N16 x K128 per 64-row half
static __device__ __forceinline__ void mma_A(
    uint32_t sb, int buf, float* scc, int g, int nh, int l15, int lh) {
    const int arow = g * 16 + l15;
    const int qrow = nh * 16 + l15;
#pragma unroll
    for (int s = 0; s < 8; s++) {
        int ch = 2 * s + lh;
        uint32_t ao = arow * 256 + ((ch ^ (arow & 7)) << 4);
        uint32_t qo = qrow * 256 + ((ch ^ (qrow & 7)) << 4);
        uint32_t aH[4], aL[4], bH[4], bL[4];
        ldm4(aH, sb + BUF(buf) + ao);
        ldm4(aL, sb + BUF(buf) + 16384 + ao);
        ldm4(bH, sb + QT_H + qo);
        ldm4(bL, sb + QT_L + qo);
        mma16816(scc + 0, aH, bH[0], bH[2]);
        mma16816(scc + 4, aH, bH[1], bH[3]);
        mma16816(scc + 0, aH, bL[0], bL[2]);
        mma16816(scc + 4, aH, bL[1], bL[3]);
        mma16816(scc + 0, aL, bH[0], bH[2]);
        mma16816(scc + 4, aL, bH[1], bH[3]);
    }
}

// Phase C: warp (hH = h-half, dQ = d-quarter); M16h x N32d over one 64-k half hc
static __device__ __forceinline__ void mma_C(
    uint32_t sb, int buf, int hc, float* oacc, int hH, int dQ, int l15, int lh, int lid) {
    const int kl = (lid & 7) + ((lid >> 4) << 3);
    const int hcL = 2 * hH + ((lid >> 3) & 1);
#pragma unroll
    for (int s = 0; s < 4; s++) {
        int kk = hc * 64 + s * 16 + kl;
        uint32_t aH[4], aL[4];
        ldm4t(aH, sb + P_HI + poff(kk, hcL));
        ldm4t(aL, sb + P_LO + poff(kk, hcL));
        int vrow = s * 16 + l15;
        uint32_t vc0 = (uint32_t)(dQ * 4 + lh), vc1 = vc0 + 2;
        uint32_t vo0 = vrow * 256 + ((vc0 ^ (vrow & 7)) << 4);
        uint32_t vo1 = vrow * 256 + ((vc1 ^ (vrow & 7)) << 4);
        uint32_t vH0[4], vH1[4], vL0[4], vL1[4];
        ldm4t(vH0, sb + BUF(buf) + vo0);
        ldm4t(vH1, sb + BUF(buf) + vo1);
        ldm4t(vL0, sb + BUF(buf) + 16384 + vo0);
        ldm4t(vL1, sb + BUF(buf) + 16384 + vo1);
        mma16816(oacc + 0,  aH, vH0[0], vH0[1]);
        mma16816(oacc + 4,  aH, vH0[2], vH0[3]);
        mma16816(oacc + 8,  aH, vH1[0], vH1[1]);
        mma16816(oacc + 12, aH, vH1[2], vH1[3]);
        mma16816(oacc + 0,  aH, vL0[0], vL0[1]);
        mma16816(oacc + 4,  aH, vL0[2], vL0[3]);
        mma16816(oacc + 8,  aH, vL1[0], vL1[1]);
        mma16816(oacc + 12, aH, vL1[2], vL1[3]);
        mma16816(oacc + 0,  aL, vH0[0], vH0[1]);
        mma16816(oacc + 4,  aL, vH0[2], vH0[3]);
        mma16816(oacc + 8,  aL, vH1[0], vH1[1]);
        mma16816(oacc + 12, aL, vH1[2], vH1[3]);
    }
}

__global__ void __launch_bounds__(256, 2)
sparse_attn_v12(const float* __restrict__ q,
                const float* __restrict__ sink, const int* __restrict__ topk,
                float* __restrict__ out) {
    extern __shared__ __align__(1024) unsigned char smem[];
    const uint32_t sb = smem_u32(smem);
    const int tid = threadIdx.x, wid = tid >> 5, lid = tid & 31;
    const int l15 = lid & 15, lh = lid >> 4;
    const int g = wid >> 1, nh = wid & 1;     // phase A role
    const int hH = wid & 1, dQ = wid >> 1;    // phase C role (dQ in 0..3, N32)
    const int sq = blockIdx.x;
    float* redm = (float*)(smem + REDM);
    float* reds = (float*)(smem + REDS);
    float* invv = (float*)(smem + INVV);
    int* sidx = (int*)(smem + SIDX);

    float sc[32];
    float oacc[16];
#pragma unroll
    for (int t = 0; t < 32; t++) sc[t] = 0.f;
#pragma unroll
    for (int t = 0; t < 16; t++) oacc[t] = 0.f;

    // ---- s0: indices + Q convert (scale + split) ----
    sidx[tid] = __ldg(topk + (long)sq * 256 + tid);
    const float* qg = q + (long)sq * 4096;
#pragma unroll
    for (int it = 0; it < 4; it++) {
        int r = wid * 4 + it;
        float4 v = *(const float4*)(qg + r * 128 + 4 * lid);
        uint32_t H01, L01, H23, L23;
        sp2(v.x * SCALE_F, v.y * SCALE_F, H01, L01);
        sp2(v.z * SCALE_F, v.w * SCALE_F, H23, L23);
        uint32_t o = r * 256 + (((lid >> 1) ^ (r & 7)) << 4) + ((lid & 1) << 3);
        *(uint2*)(smem + QT_H + o) = make_uint2(H01, H23);
        *(uint2*)(smem + QT_L + o) = make_uint2(L01, L23);
    }
    __syncthreads();
    issue_half(sb, sidx, 0, 0, 0, tid);          // K half0 -> b0

    // ---- s1..s4: Phase A ----
    CP_WAIT_ALL(); __syncthreads();
    issue_half(sb, sidx, 0, 1, 1, tid);          // K half1 -> b1
    mma_A(sb, 0, sc + 0, g, nh, l15, lh);

    CP_WAIT_ALL(); __syncthreads();
    issue_half(sb, sidx, 0, 2, 0, tid);          // K half2 -> b0
    mma_A(sb, 1, sc + 8, g, nh, l15, lh);

    CP_WAIT_ALL(); __syncthreads();
    issue_half(sb, sidx, 0, 3, 1, tid);          // K half3 -> b1
    mma_A(sb, 0, sc + 16, g, nh, l15, lh);

    CP_WAIT_ALL(); __syncthreads();
    issue_half(sb, sidx, 256, 0, 0, tid);        // V half0 -> b0
    mma_A(sb, 1, sc + 24, g, nh, l15, lh);

    // ---- s5: softmax -> k-major split P ----
    CP_WAIT_ALL(); __syncthreads();
    issue_half(sb, sidx, 256, 1, 1, tid);        // V half1 -> b1
    {
        float mx[4];
#pragma unroll
        for (int jj = 0; jj < 4; jj++) mx[jj] = -1e30f;
#pragma unroll
        for (int hc = 0; hc < 4; hc++)
#pragma unroll
            for (int f = 0; f < 2; f++) {
                float* e = sc + hc * 8 + f * 4;
                mx[f * 2 + 0] = fmaxf(mx[f * 2 + 0], fmaxf(e[0], e[2]));
                mx[f * 2 + 1] = fmaxf(mx[f * 2 + 1], fmaxf(e[1], e[3]));
            }
#pragma unroll
        for (int off = 4; off < 32; off <<= 1)
#pragma unroll
            for (int jj = 0; jj < 4; jj++)
                mx[jj] = fmaxf(mx[jj], __shfl_xor_sync(0xffffffffu, mx[jj], off));
        if (lid < 4) {
#pragma unroll
            for (int jj = 0; jj < 4; jj++)
                redm[wid * 32 + nh * 16 + (jj >> 1) * 8 + 2 * lid + (jj & 1)] = mx[jj];
        }
        __syncthreads();
        float mfin[4];
#pragma unroll
        for (int jj = 0; jj < 4; jj++) {
            int h = nh * 16 + (jj >> 1) * 8 + 2 * (lid & 3) + (jj & 1);
            float m = __ldg(sink + h);
#pragma unroll
            for (int g2 = 0; g2 < 4; g2++)
                m = fmaxf(m, redm[(g2 * 2 + nh) * 32 + h]);
            mfin[jj] = m;
        }
        float sm[4];
#pragma unroll
        for (int jj = 0; jj < 4; jj++) sm[jj] = 0.f;
#pragma unroll
        for (int hc = 0; hc < 4; hc++) {
            int kR = hc * 64 + g * 16 + (lid >> 2);
#pragma unroll
            for (int rr = 0; rr < 2; rr++) {
                int k = kR + rr * 8;
#pragma unroll
                for (int f = 0; f < 2; f++) {
                    float e0 = __expf(sc[hc * 8 + f * 4 + rr * 2 + 0] - mfin[f * 2 + 0]);
                    float e1 = __expf(sc[hc * 8 + f * 4 + rr * 2 + 1] - mfin[f * 2 + 1]);
                    sm[f * 2 + 0] += e0;
                    sm[f * 2 + 1] += e1;
                    uint32_t H, L;
                    sp2(e0, e1, H, L);
                    uint32_t o = poff(k, 2 * nh + f) + 4 * (lid & 3);
                    *(uint32_t*)(smem + P_HI + o) = H;
                    *(uint32_t*)(smem + P_LO + o) = L;
                }
            }
        }
#pragma unroll
        for (int off = 4; off < 32; off <<= 1)
#pragma unroll
            for (int jj = 0; jj < 4; jj++)
                sm[jj] += __shfl_xor_sync(0xffffffffu, sm[jj], off);
        if (lid < 4) {
#pragma unroll
            for (int jj = 0; jj < 4; jj++)
                reds[wid * 32 + nh * 16 + (jj >> 1) * 8 + 2 * lid + (jj & 1)] = sm[jj];
        }
        __syncthreads();
        if (wid == 0) {
            int h = lid, nh2 = h >> 4;
            float sk = __ldg(sink + h);
            float m = sk;
#pragma unroll
            for (int g2 = 0; g2 < 4; g2++)
                m = fmaxf(m, redm[(g2 * 2 + nh2) * 32 + h]);
            float den = __expf(sk - m);
#pragma unroll
            for (int g2 = 0; g2 < 4; g2++)
                den += reds[(g2 * 2 + nh2) * 32 + h];
            invv[h] = 1.f / den;
        }
    }

    // ---- s6..s9: Phase C ----
    CP_WAIT_ALL(); __syncthreads();
    mma_C(sb, 0, 0, oacc, hH, dQ, l15, lh, lid);   // s6: V half0 (b0)
    __syncthreads();
    issue_half(sb, sidx, 256, 2, 0, tid);          // V half2 -> b0
    mma_C(sb, 1, 1, oacc, hH, dQ, l15, lh, lid);   // s7: V half1 (b1)

    CP_WAIT_ALL(); __syncthreads();
    issue_half(sb, sidx, 256, 3, 1, tid);          // V half3 -> b1
    mma_C(sb, 0, 2, oacc, hH, dQ, l15, lh, lid);   // s8: V half2 (b0)

    CP_WAIT_ALL(); __syncthreads();
    mma_C(sb, 1, 3, oacc, hH, dQ, l15, lh, lid);   // s9: V half3 (b1)

    // ---- epilogue: normalize + store ----
    {
        const int h0 = hH * 16 + (lid >> 2);
        float iv0 = invv[h0], iv1 = invv[h0 + 8];
        float* op = out + (long)sq * 4096;
#pragma unroll
        for (int j = 0; j < 4; j++) {
            int d = dQ * 32 + 8 * j + 2 * (lid & 3);
            float* b = oacc + j * 4;
            *(float2*)(op + h0 * 128 + d) = make_float2(b[0] * iv0, b[1] * iv0);
            *(float2*)(op + (h0 + 8) * 128 + d) = make_float2(b[2] * iv1, b[3] * iv1);
        }
    }
}

extern "C" void kernel_launch(void* const* d_in, const int* in_sizes, int n_in,
                              void* d_out, int out_size) {
    (void)in_sizes; (void)n_in; (void)out_size;
    const float* q    = (const float*)d_in[0];
    const float* kv   = (const float*)d_in[1];
    const float* sink = (const float*)d_in[2];
    const int*   topk = (const int*)d_in[3];
    float* out = (float*)d_out;

    cvt_kv_kernel<<<1024, 256>>>(kv);

    cudaFuncSetAttribute(sparse_attn_v12,
                         cudaFuncAttributeMaxDynamicSharedMemorySize, SMEM_BYTES);
    sparse_attn_v12<<<2048, 256, SMEM_BYTES>>>(q, sink, topk, out);
}

// round 13
// speedup vs baseline: 1.0784x; 1.0784x over previous
#include <cuda_runtime.h>
#include <cstdint>

#define SCALE_F 0.08838834764831845f

// persistent split-bf16 KV tables (4096 rows x 256 elems), filled per launch
__device__ uint16_t g_kvh[4096 * 256];
__device__ uint16_t g_kvl[4096 * 256];

// ---------------- smem byte offsets (single-buffer, 128-thread CTA) ------
#define BUF_H  0         // 16KB: K/V half-chunk hi (64 rows x 256B)
#define BUF_L  16384     // 16KB: lo
#define QT_H   32768     // 8KB: Q hi (32 rows x 256B)
#define QT_L   40960     // 8KB: Q lo
#define P_LO   32768     // 16KB: P lo aliases QT (Q dead after phase A)
#define P_HI   49152     // 16KB: P hi (256 k x 64B, k-major)
#define REDM   65536
#define REDS   66048
#define INVV   66560
#define SIDX   66688
#define SMEM_BYTES 67712

// ---------------- helpers ----------------
static __device__ __forceinline__ uint32_t smem_u32(const void* p) {
    uint32_t a;
    asm("{ .reg .u64 t; cvta.to.shared.u64 t, %1; cvt.u32.u64 %0, t; }" : "=r"(a) : "l"(p));
    return a;
}
static __device__ __forceinline__ void ldm4(uint32_t* r, uint32_t addr) {
    asm volatile("ldmatrix.sync.aligned.m8n8.x4.shared.b16 {%0,%1,%2,%3}, [%4];"
                 : "=r"(r[0]), "=r"(r[1]), "=r"(r[2]), "=r"(r[3]) : "r"(addr));
}
static __device__ __forceinline__ void ldm4t(uint32_t* r, uint32_t addr) {
    asm volatile("ldmatrix.sync.aligned.m8n8.x4.trans.shared.b16 {%0,%1,%2,%3}, [%4];"
                 : "=r"(r[0]), "=r"(r[1]), "=r"(r[2]), "=r"(r[3]) : "r"(addr));
}
static __device__ __forceinline__ void mma16816(float* c, const uint32_t* a,
                                                uint32_t b0, uint32_t b1) {
    asm volatile("mma.sync.aligned.m16n8k16.row.col.f32.bf16.bf16.f32 "
                 "{%0,%1,%2,%3}, {%4,%5,%6,%7}, {%8,%9}, {%0,%1,%2,%3};"
                 : "+f"(c[0]), "+f"(c[1]), "+f"(c[2]), "+f"(c[3])
                 : "r"(a[0]), "r"(a[1]), "r"(a[2]), "r"(a[3]), "r"(b0), "r"(b1));
}
// pair split: H = packed (bf16t(x0), bf16t(x1)); L = packed rn-residuals
static __device__ __forceinline__ void sp2(float x0, float x1, uint32_t& H, uint32_t& L) {
    unsigned u0 = __float_as_uint(x0), u1 = __float_as_uint(x1);
    asm("prmt.b32 %0, %1, %2, 0x7632;" : "=r"(H) : "r"(u0), "r"(u1));
    float r0 = x0 - __uint_as_float(u0 & 0xFFFF0000u);
    float r1 = x1 - __uint_as_float(u1 & 0xFFFF0000u);
    asm("cvt.rn.bf16x2.f32 %0, %1, %2;" : "=r"(L) : "f"(r1), "f"(r0));
}
// k-major P byte offset for (k, h-chunk hc in 0..3): row 64B, XOR swizzle
static __device__ __forceinline__ uint32_t poff(int k, int hc) {
    return (uint32_t)(k * 64 + ((hc ^ ((k >> 1) & 3)) << 4));
}
#define CP_WAIT_ALL() asm volatile("cp.async.wait_group 0;" ::: "memory")

// ---- pre-kernel: split-convert the whole KV table once ----
__global__ void __launch_bounds__(256) cvt_kv_kernel(const float* __restrict__ kv) {
    int t = blockIdx.x * 256 + threadIdx.x;
    float4 v = *(const float4*)(kv + (long)t * 4);
    uint32_t H01, L01, H23, L23;
    sp2(v.x, v.y, H01, L01);
    sp2(v.z, v.w, H23, L23);
    *(uint2*)((char*)g_kvh + (long)t * 8) = make_uint2(H01, H23);
    *(uint2*)((char*)g_kvl + (long)t * 8) = make_uint2(L01, L23);
}

// issue cp.async for one 64-row half (hi+lo, 32KB); 128 threads, 16x16B each
static __device__ __forceinline__ void issue_half(
    uint32_t sb, const int* sidx, int base /*0=K, 256=V bytes*/,
    int hc, int tid) {
#pragma unroll
    for (int i = 0; i < 16; i++) {
        int t = i * 128 + tid;
        int rc = t >> 4, c = t & 15;
        int half = rc >> 6, r = rc & 63;
        int id = sidx[hc * 64 + r];
        const uint16_t* tbl = half ? g_kvl : g_kvh;
        const char* src = (const char*)tbl + (long)id * 512 + base + c * 16;
        uint32_t dst = sb + (half ? BUF_L : BUF_H) + r * 256 + ((c ^ (r & 7)) << 4);
        asm volatile("cp.async.cg.shared.global [%0], [%1], 16;"
                     :: "r"(dst), "l"(__cvta_generic_to_global(src)));
    }
    asm volatile("cp.async.commit_group;");
}

// Phase A: warp cw owns 16 k-rows, M16 x N32 (v10 consumer tiling, unreplicated)
static __device__ __forceinline__ void mma_A(
    uint32_t sb, float* scc, int cw, int l15, int lh) {
    const int arow = cw * 16 + l15;
    const int qrow0 = l15, qrow1 = 16 + l15;
#pragma unroll
    for (int s = 0; s < 8; s++) {
        int ch = 2 * s + lh;
        uint32_t ao = arow * 256 + ((ch ^ (arow & 7)) << 4);
        uint32_t q0 = qrow0 * 256 + ((ch ^ (qrow0 & 7)) << 4);
        uint32_t q1 = qrow1 * 256 + ((ch ^ (qrow1 & 7)) << 4);
        uint32_t aH[4], aL[4], bH0[4], bH1[4], bL0[4], bL1[4];
        ldm4(aH, sb + BUF_H + ao);
        ldm4(aL, sb + BUF_L + ao);
        ldm4(bH0, sb + QT_H + q0);
        ldm4(bH1, sb + QT_H + q1);
        ldm4(bL0, sb + QT_L + q0);
        ldm4(bL1, sb + QT_L + q1);
        mma16816(scc + 0,  aH, bH0[0], bH0[2]);
        mma16816(scc + 4,  aH, bH0[1], bH0[3]);
        mma16816(scc + 8,  aH, bH1[0], bH1[2]);
        mma16816(scc + 12, aH, bH1[1], bH1[3]);
        mma16816(scc + 0,  aH, bL0[0], bL0[2]);
        mma16816(scc + 4,  aH, bL0[1], bL0[3]);
        mma16816(scc + 8,  aH, bL1[0], bL1[2]);
        mma16816(scc + 12, aH, bL1[1], bL1[3]);
        mma16816(scc + 0,  aL, bH0[0], bH0[2]);
        mma16816(scc + 4,  aL, bH0[1], bH0[3]);
        mma16816(scc + 8,  aL, bH1[0], bH1[2]);
        mma16816(scc + 12, aL, bH1[1], bH1[3]);
    }
}

// Phase C: warp cw = d-quarter, M32h x N32d over one 64-k half hcl
static __device__ __forceinline__ void mma_C(
    uint32_t sb, int hcl, float* oacc, int cw, int l15, int lh, int lid) {
    const int kl = (lid & 7) + ((lid >> 4) << 3);
    const int hcL = (lid >> 3) & 1;
#pragma unroll
    for (int s = 0; s < 4; s++) {
        int kk = hcl * 64 + s * 16 + kl;
        uint32_t adr0 = poff(kk, hcL);        // h0-15
        uint32_t adr1 = poff(kk, 2 + hcL);    // h16-31
        uint32_t aH0[4], aH1[4], aL0[4], aL1[4];
        ldm4t(aH0, sb + P_HI + adr0);
        ldm4t(aH1, sb + P_HI + adr1);
        ldm4t(aL0, sb + P_LO + adr0);
        ldm4t(aL1, sb + P_LO + adr1);
        int vrow = s * 16 + l15;
        uint32_t vc0 = cw * 4 + lh, vc1 = vc0 + 2;
        uint32_t v0 = vrow * 256 + ((vc0 ^ (vrow & 7)) << 4);
        uint32_t v1 = vrow * 256 + ((vc1 ^ (vrow & 7)) << 4);
        uint32_t vH0[4], vH1[4], vL0[4], vL1[4];
        ldm4t(vH0, sb + BUF_H + v0);
        ldm4t(vH1, sb + BUF_H + v1);
        ldm4t(vL0, sb + BUF_L + v0);
        ldm4t(vL1, sb + BUF_L + v1);
        mma16816(oacc + 0,  aH0, vH0[0], vH0[1]);
        mma16816(oacc + 4,  aH0, vH0[2], vH0[3]);
        mma16816(oacc + 8,  aH0, vH1[0], vH1[1]);
        mma16816(oacc + 12, aH0, vH1[2], vH1[3]);
        mma16816(oacc + 16, aH1, vH0[0], vH0[1]);
        mma16816(oacc + 20, aH1, vH0[2], vH0[3]);
        mma16816(oacc + 24, aH1, vH1[0], vH1[1]);
        mma16816(oacc + 28, aH1, vH1[2], vH1[3]);
        mma16816(oacc + 0,  aH0, vL0[0], vL0[1]);
        mma16816(oacc + 4,  aH0, vL0[2], vL0[3]);
        mma16816(oacc + 8,  aH0, vL1[0], vL1[1]);
        mma16816(oacc + 12, aH0, vL1[2], vL1[3]);
        mma16816(oacc + 16, aH1, vL0[0], vL0[1]);
        mma16816(oacc + 20, aH1, vL0[2], vL0[3]);
        mma16816(oacc + 24, aH1, vL1[0], vL1[1]);
        mma16816(oacc + 28, aH1, vL1[2], vL1[3]);
        mma16816(oacc + 0,  aL0, vH0[0], vH0[1]);
        mma16816(oacc + 4,  aL0, vH0[2], vH0[3]);
        mma16816(oacc + 8,  aL0, vH1[0], vH1[1]);
        mma16816(oacc + 12, aL0, vH1[2], vH1[3]);
        mma16816(oacc + 16, aL1, vH0[0], vH0[1]);
        mma16816(oacc + 20, aL1, vH0[2], vH0[3]);
        mma16816(oacc + 24, aL1, vH1[0], vH1[1]);
        mma16816(oacc + 28, aL1, vH1[2], vH1[3]);
    }
}

__global__ void __launch_bounds__(128, 3)
sparse_attn_v13(const float* __restrict__ q,
                const float* __restrict__ sink, const int* __restrict__ topk,
                float* __restrict__ out) {
    extern __shared__ __align__(1024) unsigned char smem[];
    const uint32_t sb = smem_u32(smem);
    const int tid = threadIdx.x, wid = tid >> 5, lid = tid & 31;
    const int l15 = lid & 15, lh = lid >> 4;
    const int cw = wid;                       // 4 warps, v10 consumer roles
    const int sq = blockIdx.x;
    float* redm = (float*)(smem + REDM);
    float* reds = (float*)(smem + REDS);
    float* invv = (float*)(smem + INVV);
    int*   sidx = (int*)(smem + SIDX);

    float sc[64];
#pragma unroll
    for (int t = 0; t < 64; t++) sc[t] = 0.f;

    // ---- s0: indices + Q convert ----
    sidx[tid]       = __ldg(topk + (long)sq * 256 + tid);
    sidx[tid + 128] = __ldg(topk + (long)sq * 256 + 128 + tid);
    const float* qg = q + (long)sq * 4096;
#pragma unroll
    for (int bb = 0; bb < 2; bb++) {
        float4 v[4];
        int r[4];
#pragma unroll
        for (int it = 0; it < 4; it++) {
            r[it] = cw * 8 + bb * 4 + it;
            v[it] = *(const float4*)(qg + r[it] * 128 + 4 * lid);
        }
#pragma unroll
        for (int it = 0; it < 4; it++) {
            uint32_t H01, L01, H23, L23;
            sp2(v[it].x * SCALE_F, v[it].y * SCALE_F, H01, L01);
            sp2(v[it].z * SCALE_F, v[it].w * SCALE_F, H23, L23);
            uint32_t o = r[it] * 256 + (((lid >> 1) ^ (r[it] & 7)) << 4) + ((lid & 1) << 3);
            *(uint2*)(smem + QT_H + o) = make_uint2(H01, H23);
            *(uint2*)(smem + QT_L + o) = make_uint2(L01, L23);
        }
    }
    __syncthreads();
    issue_half(sb, sidx, 0, 0, tid);             // K half0

    // ---- Phase A: 4 single-buffered steps ----
#pragma unroll
    for (int hc = 0; hc < 4; hc++) {
        CP_WAIT_ALL();
        __syncthreads();                          // buffer filled & visible
        mma_A(sb, sc + hc * 16, cw, l15, lh);
        __syncthreads();                          // buffer free
        if (hc < 3) issue_half(sb, sidx, 0, hc + 1, tid);
        else        issue_half(sb, sidx, 256, 0, tid);   // V half0
    }

    // ---- softmax (runs under the V0 copy) -> k-major split P ----
    {
        float mx[8];
#pragma unroll
        for (int jj = 0; jj < 8; jj++) mx[jj] = -1e30f;
#pragma unroll
        for (int t = 0; t < 2; t++)
#pragma unroll
            for (int j = 0; j < 4; j++) {
                float* f = sc + 16 * (2 * t) + 4 * j;
                float* g = sc + 16 * (2 * t + 1) + 4 * j;
                mx[2 * j + 0] = fmaxf(mx[2 * j + 0],
                                      fmaxf(fmaxf(f[0], f[2]), fmaxf(g[0], g[2])));
                mx[2 * j + 1] = fmaxf(mx[2 * j + 1],
                                      fmaxf(fmaxf(f[1], f[3]), fmaxf(g[1], g[3])));
            }
#pragma unroll
        for (int off = 4; off < 32; off <<= 1)
#pragma unroll
            for (int jj = 0; jj < 8; jj++)
                mx[jj] = fmaxf(mx[jj], __shfl_xor_sync(0xffffffffu, mx[jj], off));
        if (lid < 4) {
#pragma unroll
            for (int jj = 0; jj < 8; jj++)
                redm[cw * 32 + 8 * (jj >> 1) + 2 * lid + (jj & 1)] = mx[jj];
        }
        __syncthreads();
        float mfin[8];
#pragma unroll
        for (int jj = 0; jj < 8; jj++) {
            int h = 8 * (jj >> 1) + 2 * (lid & 3) + (jj & 1);
            float m = __ldg(sink + h);
#pragma unroll
            for (int w = 0; w < 4; w++) m = fmaxf(m, redm[w * 32 + h]);
            mfin[jj] = m;
        }
        float sm[8];
#pragma unroll
        for (int jj = 0; jj < 8; jj++) sm[jj] = 0.f;
#pragma unroll
        for (int hc = 0; hc < 4; hc++)
#pragma unroll
            for (int j = 0; j < 4; j++) {
                int kb = hc * 64 + cw * 16 + (lid >> 2);
                float e0 = __expf(sc[hc * 16 + 4 * j + 0] - mfin[2 * j + 0]);
                float e1 = __expf(sc[hc * 16 + 4 * j + 1] - mfin[2 * j + 1]);
                float e2 = __expf(sc[hc * 16 + 4 * j + 2] - mfin[2 * j + 0]);
                float e3 = __expf(sc[hc * 16 + 4 * j + 3] - mfin[2 * j + 1]);
                sm[2 * j + 0] += e0 + e2;
                sm[2 * j + 1] += e1 + e3;
                uint32_t H01, L01, H23, L23;
                sp2(e0, e1, H01, L01);
                sp2(e2, e3, H23, L23);
                uint32_t o0 = poff(kb, j) + 4 * (lid & 3);
                uint32_t o2 = poff(kb + 8, j) + 4 * (lid & 3);
                *(uint32_t*)(smem + P_HI + o0) = H01;
                *(uint32_t*)(smem + P_LO + o0) = L01;
                *(uint32_t*)(smem + P_HI + o2) = H23;
                *(uint32_t*)(smem + P_LO + o2) = L23;
            }
#pragma unroll
        for (int off = 4; off < 32; off <<= 1)
#pragma unroll
            for (int jj = 0; jj < 8; jj++)
                sm[jj] += __shfl_xor_sync(0xffffffffu, sm[jj], off);
        if (lid < 4) {
#pragma unroll
            for (int jj = 0; jj < 8; jj++)
                reds[cw * 32 + 8 * (jj >> 1) + 2 * lid + (jj & 1)] = sm[jj];
        }
        __syncthreads();
        if (wid == 0) {
            int h = lid;
            float sk = __ldg(sink + h);
            float m = sk;
#pragma unroll
            for (int w = 0; w < 4; w++) m = fmaxf(m, redm[w * 32 + h]);
            float den = __expf(sk - m);
#pragma unroll
            for (int w = 0; w < 4; w++) den += reds[w * 32 + h];
            invv[h] = 1.f / den;
        }
    }

    float oacc[32];
#pragma unroll
    for (int t = 0; t < 32; t++) oacc[t] = 0.f;

    // ---- Phase C: 4 single-buffered steps ----
#pragma unroll
    for (int hc = 0; hc < 4; hc++) {
        CP_WAIT_ALL();
        __syncthreads();                          // V half ready (P also visible on hc=0)
        mma_C(sb, hc, oacc, cw, l15, lh, lid);
        __syncthreads();                          // buffer free
        if (hc < 3) issue_half(sb, sidx, 256, hc + 1, tid);
    }

    // ---- epilogue: normalize + store ----
    {
#pragma unroll
        for (int i = 0; i < 2; i++) {
            int h0 = 16 * i + (lid >> 2);
            float iv0 = invv[h0], iv1 = invv[h0 + 8];
            float* op = out + (long)sq * 4096;
#pragma unroll
            for (int j = 0; j < 4; j++) {
                int d = cw * 32 + 8 * j + 2 * (lid & 3);
                float* b = oacc + i * 16 + j * 4;
                *(float2*)(op + h0 * 128 + d) = make_float2(b[0] * iv0, b[1] * iv0);
                *(float2*)(op + (h0 + 8) * 128 + d) = make_float2(b[2] * iv1, b[3] * iv1);
            }
        }
    }
}

extern "C" void kernel_launch(void* const* d_in, const int* in_sizes, int n_in,
                              void* d_out, int out_size) {
    (void)in_sizes; (void)n_in; (void)out_size;
    const float* q    = (const float*)d_in[0];
    const float* kv   = (const float*)d_in[1];
    const float* sink = (const float*)d_in[2];
    const int*   topk = (const int*)d_in[3];
    float* out = (float*)d_out;

    cvt_kv_kernel<<<1024, 256>>>(kv);

    cudaFuncSetAttribute(sparse_attn_v13,
                         cudaFuncAttributeMaxDynamicSharedMemorySize, SMEM_BYTES);
    sparse_attn_v13<<<2048, 128, SMEM_BYTES>>>(q, sink, topk, out);
}